// round 10
// baseline (speedup 1.0000x reference)
#include <cuda_runtime.h>
#include <cuda_fp16.h>
#include <cstdint>

#define NN      50000
#define HID     512
#define OUT_DIM 256
#define E_TILE  64
#define THREADS 512
#define GRID    148
#define APITCH  264   // uint32 (fp16-pair) row pitch; conflict-free frag LDS64

// ---------------- device scratch ----------------
__device__ __align__(16) uint32_t g_PDp[(size_t)NN * 256];  // fp16 pairs, A-layout, incl. +b1
__device__ __align__(16) uint32_t g_PSp[(size_t)NN * 256];  // fp16 pairs, A-layout
__device__ __align__(16) float    g_W1comb[160 * HID];
__device__ __align__(16) float    g_W1c[32 * HID];
__device__ __align__(16) uint32_t g_W2p[HID * HID / 2];     // fp16 pair-permuted
__device__ __align__(16) uint32_t g_W3p[HID * OUT_DIM / 2]; // fp16 pair-permuted
__device__ __align__(16) uint32_t g_w320p[256];             // W1 row 320, fp16 pairs, A-layout

__device__ __forceinline__ float tf32r(float x) {
    unsigned u; asm("cvt.rna.tf32.f32 %0, %1;" : "=r"(u) : "f"(x));
    return __uint_as_float(u);
}
__device__ __forceinline__ uint32_t packh2(float lo, float hi) {
    uint32_t u; asm("cvt.rn.f16x2.f32 %0, %1, %2;" : "=r"(u) : "f"(hi), "f"(lo));
    return u;
}
__device__ __forceinline__ uint32_t h2_gather(uint32_t pd, uint32_t ps, uint32_t w,
                                              uint32_t d2) {
    uint32_t s, r;
    asm("add.rn.f16x2 %0, %1, %2;" : "=r"(s) : "r"(pd), "r"(ps));
    asm("fma.rn.f16x2 %0, %1, %2, %3;" : "=r"(r) : "r"(d2), "r"(w), "r"(s));
    asm("max.f16x2 %0, %1, %2;" : "=r"(r) : "r"(r), "r"(0u));
    return r;
}
__device__ __forceinline__ void cp16(uint32_t saddr, const void* gptr) {
    asm volatile("cp.async.ca.shared.global [%0], [%1], 16;" :: "r"(saddr), "l"(gptr));
}
__device__ __forceinline__ void cp_commit() { asm volatile("cp.async.commit_group;"); }
template <int N> __device__ __forceinline__ void cp_wait() {
    asm volatile("cp.async.wait_group %0;" :: "n"(N));
}
__device__ __forceinline__ uint32_t s2u(const void* p) {
    uint32_t a;
    asm("{ .reg .u64 t; cvta.to.shared.u64 t, %1; cvt.u32.u64 %0, t; }" : "=r"(a) : "l"(p));
    return a;
}
__device__ __forceinline__ void mma_tf32s(float c[4], const uint32_t a[4],
                                          uint32_t b0, uint32_t b1) {
    asm volatile(
        "mma.sync.aligned.m16n8k8.row.col.f32.tf32.tf32.f32 "
        "{%0,%1,%2,%3}, {%4,%5,%6,%7}, {%8,%9}, {%0,%1,%2,%3};"
        : "+f"(c[0]), "+f"(c[1]), "+f"(c[2]), "+f"(c[3])
        : "r"(a[0]), "r"(a[1]), "r"(a[2]), "r"(a[3]), "r"(b0), "r"(b1));
}
__device__ __forceinline__ void mma_h(float c[4], uint32_t a0, uint32_t a1,
                                      uint32_t a2, uint32_t a3,
                                      uint32_t b0, uint32_t b1) {
    asm volatile(
        "mma.sync.aligned.m16n8k16.row.col.f32.f16.f16.f32 "
        "{%0,%1,%2,%3}, {%4,%5,%6,%7}, {%8,%9}, {%0,%1,%2,%3};"
        : "+f"(c[0]), "+f"(c[1]), "+f"(c[2]), "+f"(c[3])
        : "r"(a0), "r"(a1), "r"(a2), "r"(a3), "r"(b0), "r"(b1));
}
__device__ __forceinline__ int slotp(int p) { return ((p & 3) << 1) | (p >> 2); }
__device__ __forceinline__ int poff(int c) { return ((c >> 4) << 3) + slotp((c >> 1) & 7); }

// ================= prologue 0: weight transforms =================
__global__ void conv_kernel(const float* __restrict__ W1, const float* __restrict__ W2,
                            const float* __restrict__ W3) {
    int i = blockIdx.x * blockDim.x + threadIdx.x;
    if (i < 160 * 512) {
        int r = i >> 9, c = i & 511;
        float v = W1[r * 512 + c];
        if (r >= 32) v += W1[(r + 160) * 512 + c];
        g_W1comb[i] = tf32r(v);
        return;
    }
    i -= 160 * 512;
    if (i < 32 * 512) {
        int r = i >> 9, c = i & 511;
        g_W1c[i] = tf32r(W1[(160 + r) * 512 + c]);
        return;
    }
    i -= 32 * 512;
    if (i < 512 * 512 / 2) {
        int kp = i >> 9, n = i & 511;
        int k = kp << 1;
        g_W2p[(size_t)((kp >> 3) * 512 + n) * 8 + slotp(kp & 7)] =
            packh2(W2[k * 512 + n], W2[(k + 1) * 512 + n]);
        return;
    }
    i -= 512 * 512 / 2;
    if (i < 512 * 256 / 2) {
        int kp = i >> 8, n = i & 255;
        int k = kp << 1;
        g_W3p[(size_t)((kp >> 3) * 256 + n) * 8 + slotp(kp & 7)] =
            packh2(W3[k * 256 + n], W3[(k + 1) * 256 + n]);
        return;
    }
    i -= 512 * 256 / 2;
    if (i < 256) {
        int c = i << 1;
        g_w320p[poff(c)] = packh2(W1[320 * 512 + c], W1[320 * 512 + c + 1]);
    }
}

// ================= prologue GEMM machinery (tf32, proven) =================
template <int N, int NT, int NSTG, int NTHR>
__device__ __forceinline__ void run_gemm(const float* __restrict__ Wg,
                                         const float* __restrict__ As, int lda,
                                         float* Bst, float (&acc)[2][8][4],
                                         int wm, int wn, int g, int tig, int tid) {
    constexpr int BLD = N + 8;
    constexpr int CP_ITERS = (16 * N / 4) / NTHR;
    uint32_t bst_base = s2u(Bst);
#pragma unroll
    for (int mt = 0; mt < 2; mt++)
#pragma unroll
        for (int nt = 0; nt < NT; nt++)
#pragma unroll
            for (int r = 0; r < 4; r++) acc[mt][nt][r] = 0.f;

    auto stage_cp = [&](int s, int buf) {
#pragma unroll
        for (int it = 0; it < CP_ITERS; it++) {
            int idx = it * NTHR + tid;
            int r = idx / (N / 4), c = idx % (N / 4);
            uint32_t dst = bst_base + (uint32_t)((buf * 16 + r) * BLD + c * 4) * 4u;
            cp16(dst, Wg + (size_t)(s * 16 + r) * N + c * 4);
        }
        cp_commit();
    };

    stage_cp(0, 0);
    for (int s = 0; s < NSTG; s++) {
        if (s + 1 < NSTG) { stage_cp(s + 1, (s + 1) & 1); cp_wait<1>(); }
        else              { cp_wait<0>(); }
        __syncthreads();
        const float* B = Bst + (s & 1) * 16 * BLD;
#pragma unroll
        for (int k8 = 0; k8 < 2; k8++) {
            int kg = s * 16 + k8 * 8;
            uint32_t a[2][4];
#pragma unroll
            for (int mt = 0; mt < 2; mt++) {
                const float* ar = As + (wm * 32 + mt * 16 + g) * lda + kg + tig;
                a[mt][0] = __float_as_uint(ar[0]);
                a[mt][1] = __float_as_uint(ar[8 * lda]);
                a[mt][2] = __float_as_uint(ar[4]);
                a[mt][3] = __float_as_uint(ar[8 * lda + 4]);
            }
#pragma unroll
            for (int nt = 0; nt < NT; nt++) {
                int col = wn * (NT * 8) + nt * 8 + g;
                uint32_t b0 = __float_as_uint(B[(k8 * 8 + tig) * BLD + col]);
                uint32_t b1 = __float_as_uint(B[(k8 * 8 + tig + 4) * BLD + col]);
                mma_tf32s(acc[0][nt], a[0], b0, b1);
                mma_tf32s(acc[1][nt], a[1], b0, b1);
            }
        }
        __syncthreads();
    }
}

// ================= prologue 1: per-node PD/PS (fp16 pair output) =================
__global__ void __launch_bounds__(512, 1)
pdps_kernel(const float* __restrict__ nf, const float* __restrict__ nh,
            const float* __restrict__ b1) {
    extern __shared__ float sm[];
    float* As = sm;               // [64][164]
    float* Bst = sm + 64 * 164;   // [2][16][520]
    int tid = threadIdx.x, wid = tid >> 5, lane = tid & 31;
    int g = lane >> 2, tig = lane & 3, wm = wid >> 3, wn = wid & 7;
    int n0 = blockIdx.x * 64;
    {
        int rr = wid * 4;
#pragma unroll
        for (int q = 0; q < 4; q++) {
            int r = rr + q, n = n0 + r;
            bool ok = n < NN; int ni = ok ? n : 0;
            float* ar = As + r * 164;
            ar[lane] = ok ? tf32r(nf[(size_t)ni * 32 + lane]) : 0.f;
#pragma unroll
            for (int j = 0; j < 4; j++)
                ar[32 + j * 32 + lane] = ok ? tf32r(nh[(size_t)ni * 128 + j * 32 + lane]) : 0.f;
            if (lane < 4) ar[160 + lane] = 0.f;
        }
    }
    __syncthreads();
    float acc[2][8][4];
    run_gemm<512, 8, 10, 512>(g_W1comb, As, 164, Bst, acc, wm, wn, g, tig, tid);
#pragma unroll
    for (int mt = 0; mt < 2; mt++)
#pragma unroll
        for (int nt = 0; nt < 8; nt++) {
            int c = wn * 64 + nt * 8 + 2 * tig;
            float bb0 = __ldg(&b1[c]), bb1 = __ldg(&b1[c + 1]);
            int r0 = wm * 32 + mt * 16 + g;
            int off = poff(c);
            if (n0 + r0 < NN)
                g_PDp[(size_t)(n0 + r0) * 256 + off] =
                    packh2(acc[mt][nt][0] + bb0, acc[mt][nt][1] + bb1);
            if (n0 + r0 + 8 < NN)
                g_PDp[(size_t)(n0 + r0 + 8) * 256 + off] =
                    packh2(acc[mt][nt][2] + bb0, acc[mt][nt][3] + bb1);
        }
    run_gemm<512, 8, 2, 512>(g_W1c, As, 164, Bst, acc, wm, wn, g, tig, tid);
#pragma unroll
    for (int mt = 0; mt < 2; mt++)
#pragma unroll
        for (int nt = 0; nt < 8; nt++) {
            int c = wn * 64 + nt * 8 + 2 * tig;
            int r0 = wm * 32 + mt * 16 + g;
            int off = poff(c);
            if (n0 + r0 < NN)
                g_PSp[(size_t)(n0 + r0) * 256 + off] =
                    packh2(acc[mt][nt][0], acc[mt][nt][1]);
            if (n0 + r0 + 8 < NN)
                g_PSp[(size_t)(n0 + r0 + 8) * 256 + off] =
                    packh2(acc[mt][nt][2], acc[mt][nt][3]);
        }
}

// ================= main persistent kernel (layers 2+3) =================
// smem u32 map
#define SM_AU0  0
#define SM_AU1  16896
#define SM_BU   33792
#define SM_SD   50176
#define SM_SS   50240
#define SM_SDI  50304
#define SM_B2   50368
#define SM_B3   50880
#define SM_TOT  51136

// One GEMM over 16 k=32 stages; B pipeline is GLOBAL: during stage s we copy
// schedule-stage s+1 (crossing into the other layer / next tile at s==15).
// HALF=0: this GEMM consumes W2, next is W3. HALF=1: consumes W3, next is W2.
template <int N, int NT, int HALF>
__device__ __forceinline__ void gemm_h(const uint32_t* __restrict__ Au, uint32_t* Bu,
                                       float (&acc)[2][8][4],
                                       int wm, int wn, int g, int tig, int tid) {
    uint32_t bbase = s2u(Bu);
#pragma unroll
    for (int mt = 0; mt < 2; mt++)
#pragma unroll
        for (int nt = 0; nt < NT; nt++)
#pragma unroll
            for (int r = 0; r < 4; r++) acc[mt][nt][r] = 0.f;

    auto cpW2s = [&](int s, int buf) {
        const uint32_t* src = g_W2p + (size_t)s * 8192;
        uint32_t dst = bbase + (uint32_t)buf * 32768u;
#pragma unroll
        for (int it = 0; it < 4; it++) {
            int idx = it * THREADS + tid;
            cp16(dst + (uint32_t)idx * 16u, src + idx * 4);
        }
        cp_commit();
    };
    auto cpW3s = [&](int s, int buf) {
        const uint32_t* src = g_W3p + (size_t)s * 4096;
        uint32_t dst = bbase + (uint32_t)buf * 32768u;
#pragma unroll
        for (int it = 0; it < 2; it++) {
            int idx = it * THREADS + tid;
            cp16(dst + (uint32_t)idx * 16u, src + idx * 4);
        }
        cp_commit();
    };

    const uint32_t* arow0 = Au + (wm * 32 + g) * APITCH + tig * 2;
    for (int s = 0; s < 16; s++) {
        cp_wait<0>();
        __syncthreads();
        int s1 = s + 1, buf = s1 & 1;   // s1==16 -> buf 0 (boundary copy)
        if (HALF == 0) { if (s1 < 16) cpW2s(s1, buf); else cpW3s(0, 0); }
        else           { if (s1 < 16) cpW3s(s1, buf); else cpW2s(0, 0); }
        const uint32_t* B = Bu + (s & 1) * 8192;
#pragma unroll
        for (int kg = 0; kg < 2; kg++) {
            uint2 alo[2], ahi[2];
#pragma unroll
            for (int mt = 0; mt < 2; mt++) {
                const uint32_t* ar = arow0 + mt * (16 * APITCH) + (s * 2 + kg) * 8;
                alo[mt] = *(const uint2*)ar;
                ahi[mt] = *(const uint2*)(ar + 8 * APITCH);
            }
#pragma unroll
            for (int nt = 0; nt < NT; nt++) {
                int col = wn * (NT * 8) + nt * 8 + g;
                uint2 pb = *(const uint2*)(B + kg * (N * 8) + col * 8 + tig * 2);
                mma_h(acc[0][nt], alo[0].x, ahi[0].x, alo[0].y, ahi[0].y, pb.x, pb.y);
                mma_h(acc[1][nt], alo[1].x, ahi[1].x, alo[1].y, ahi[1].y, pb.x, pb.y);
            }
        }
    }
    __syncthreads();
}

__global__ void __launch_bounds__(THREADS, 1)
edge_kernel(const int* __restrict__ src_idx, const int* __restrict__ dst_idx,
            const float* __restrict__ dist,
            const float* __restrict__ b2, const float* __restrict__ b3,
            float* __restrict__ out, int E) {
    extern __shared__ uint32_t smu[];
    uint32_t* Bu = smu + SM_BU;
    int* sd = (int*)(smu + SM_SD);
    int* ss = (int*)(smu + SM_SS);
    float* sdist = (float*)(smu + SM_SDI);
    float* sb2 = (float*)(smu + SM_B2);
    float* sb3 = (float*)(smu + SM_B3);

    int tid = threadIdx.x, wid = tid >> 5, lane = tid & 31;
    int g = lane >> 2, tig = lane & 3, wm = wid >> 3, wn = wid & 7;
    const int stride_e = GRID * E_TILE;
    int e0 = blockIdx.x * E_TILE;
    if (e0 >= E) return;

    // ---- one-time prologue ----
    sb2[tid] = b2[tid];
    if (tid < 256) sb3[tid] = b3[tid];
    {   // indices for first tile + first weight stage copy
        int my_d = 0, my_s = 0; float my_dist = 0.f;
        if (tid < E_TILE) {
            int e = e0 + tid;
            bool ok = e < E;
            my_d = ok ? dst_idx[e] : 0;
            my_s = ok ? src_idx[e] : 0;
            my_dist = ok ? dist[e] : 0.f;
        }
        {   // cpW2 stage 0 -> buf 0
            uint32_t bbase = s2u(Bu);
#pragma unroll
            for (int it = 0; it < 4; it++) {
                int idx = it * THREADS + tid;
                cp16(bbase + (uint32_t)idx * 16u, g_W2p + idx * 4);
            }
            cp_commit();
        }
        if (tid < E_TILE) { sd[tid] = my_d; ss[tid] = my_s; sdist[tid] = my_dist; }
        __syncthreads();
        // gather tile0 -> Au0
        uint32_t* Au0 = smu + SM_AU0;
#pragma unroll
        for (int it = 0; it < 8; it++) {
            int idx4 = it * THREADS + tid;
            int e = idx4 >> 6, i = (idx4 & 63) * 4;
            uint4 pd = __ldg((const uint4*)(g_PDp + (size_t)sd[e] * 256 + i));
            uint4 ps = __ldg((const uint4*)(g_PSp + (size_t)ss[e] * 256 + i));
            uint4 w  = __ldg((const uint4*)(g_w320p + i));
            uint32_t d2 = packh2(sdist[e], sdist[e]);
            uint4 v;
            v.x = h2_gather(pd.x, ps.x, w.x, d2);
            v.y = h2_gather(pd.y, ps.y, w.y, d2);
            v.z = h2_gather(pd.z, ps.z, w.z, d2);
            v.w = h2_gather(pd.w, ps.w, w.w, d2);
            *(uint4*)(Au0 + e * APITCH + i) = v;
        }
        __syncthreads();
    }

    float acc[2][8][4];
    int p = 0;

    // ---- persistent tile loop ----
    for (; e0 < E; e0 += stride_e) {
        uint32_t* Aup = smu + (p ? SM_AU1 : SM_AU0);
        uint32_t* Auq = smu + (p ? SM_AU0 : SM_AU1);

        // layer 2
        gemm_h<HID, 8, 0>(Aup, Bu, acc, wm, wn, g, tig, tid);
        // epilogue: relu(acc + b2) -> Aup (h1 dead)
#pragma unroll
        for (int mt = 0; mt < 2; mt++)
#pragma unroll
            for (int nt = 0; nt < 8; nt++) {
                int c = wn * 64 + nt * 8 + 2 * tig;
                float2 bb = *(const float2*)(sb2 + c);
                int r0 = wm * 32 + mt * 16 + g;
                int off = poff(c);
                Aup[r0 * APITCH + off] =
                    packh2(fmaxf(acc[mt][nt][0] + bb.x, 0.f), fmaxf(acc[mt][nt][1] + bb.y, 0.f));
                Aup[(r0 + 8) * APITCH + off] =
                    packh2(fmaxf(acc[mt][nt][2] + bb.x, 0.f), fmaxf(acc[mt][nt][3] + bb.y, 0.f));
            }
        __syncthreads();

        // layer 3
        gemm_h<OUT_DIM, 4, 1>(Aup, Bu, acc, wm, wn, g, tig, tid);

        // fused phase: gather(t+1) -> Auq interleaved with output STG of t
        int e0n = e0 + stride_e;
        bool hn = e0n < E;
        if (hn && tid < E_TILE) {
            int e = e0n + tid;
            bool ok = e < E;
            sd[tid] = ok ? dst_idx[e] : 0;
            ss[tid] = ok ? src_idx[e] : 0;
            sdist[tid] = ok ? dist[e] : 0.f;
        }
        __syncthreads();
#pragma unroll
        for (int c = 0; c < 8; c++) {
            if (hn) {
                int idx4 = c * THREADS + tid;
                int e = idx4 >> 6, i = (idx4 & 63) * 4;
                uint4 pd = __ldg((const uint4*)(g_PDp + (size_t)sd[e] * 256 + i));
                uint4 ps = __ldg((const uint4*)(g_PSp + (size_t)ss[e] * 256 + i));
                uint4 w  = __ldg((const uint4*)(g_w320p + i));
                uint32_t d2 = packh2(sdist[e], sdist[e]);
                uint4 v;
                v.x = h2_gather(pd.x, ps.x, w.x, d2);
                v.y = h2_gather(pd.y, ps.y, w.y, d2);
                v.z = h2_gather(pd.z, ps.z, w.z, d2);
                v.w = h2_gather(pd.w, ps.w, w.w, d2);
                *(uint4*)(Auq + e * APITCH + i) = v;
            }
            int mt = c >> 2, nt = c & 3;
            int c0 = wn * 32 + nt * 8 + 2 * tig;
            float2 bb = *(const float2*)(sb3 + c0);
            int r0 = wm * 32 + mt * 16 + g;
            int edge0 = e0 + r0;
            if (edge0 < E)
                __stcs((float2*)(out + (size_t)edge0 * OUT_DIM + c0),
                       make_float2(acc[mt][nt][0] + bb.x, acc[mt][nt][1] + bb.y));
            int edge1 = edge0 + 8;
            if (edge1 < E)
                __stcs((float2*)(out + (size_t)edge1 * OUT_DIM + c0),
                       make_float2(acc[mt][nt][2] + bb.x, acc[mt][nt][3] + bb.y));
        }
        p ^= 1;
    }
    cp_wait<0>();   // drain the tail boundary copy before exit
}

extern "C" void kernel_launch(void* const* d_in, const int* in_sizes, int n_in,
                              void* d_out, int out_size) {
    const float* nf   = (const float*)d_in[0];
    const float* nh   = (const float*)d_in[1];
    const int*   srci = (const int*)d_in[2];
    const int*   dsti = (const int*)d_in[3];
    const float* dist = (const float*)d_in[4];
    const float* W1   = (const float*)d_in[5];
    const float* b1   = (const float*)d_in[6];
    const float* W2   = (const float*)d_in[7];
    const float* b2   = (const float*)d_in[8];
    const float* W3   = (const float*)d_in[9];
    const float* b3   = (const float*)d_in[10];
    float* out = (float*)d_out;
    int E = in_sizes[2];

    const int total_c = 160 * 512 + 32 * 512 + 512 * 512 / 2 + 512 * 256 / 2 + 256;
    conv_kernel<<<(total_c + 511) / 512, 512>>>(W1, W2, W3);

    const int pro_smem = (64 * 164 + 2 * 16 * 520) * (int)sizeof(float);
    cudaFuncSetAttribute(pdps_kernel, cudaFuncAttributeMaxDynamicSharedMemorySize, pro_smem);
    pdps_kernel<<<(NN + 63) / 64, 512, pro_smem>>>(nf, nh, b1);

    const int main_smem = SM_TOT * 4;   // 204544 bytes
    cudaFuncSetAttribute(edge_kernel, cudaFuncAttributeMaxDynamicSharedMemorySize, main_smem);
    edge_kernel<<<GRID, THREADS, main_smem>>>(srci, dsti, dist, b2, b3, out, E);
}

// round 11
// speedup vs baseline: 1.1181x; 1.1181x over previous
#include <cuda_runtime.h>
#include <cuda_fp16.h>
#include <cstdint>

#define NN      50000
#define HID     512
#define OUT_DIM 256
#define E_TILE  64
#define THREADS 512
#define APITCH  264   // uint32 (fp16-pair) row pitch; conflict-free frag LDS64
#define BSTRIDE 8192  // u32 stride between B buffers (32 KB)

// ---------------- device scratch ----------------
__device__ __align__(16) uint32_t g_PDp[(size_t)NN * 256];  // fp16 pairs, A-layout, incl. +b1
__device__ __align__(16) uint32_t g_PSp[(size_t)NN * 256];  // fp16 pairs, A-layout
__device__ __align__(16) float    g_W1comb[160 * HID];
__device__ __align__(16) float    g_W1c[32 * HID];
__device__ __align__(16) uint32_t g_W2p[HID * HID / 2];     // fp16 pair-permuted
__device__ __align__(16) uint32_t g_W3p[HID * OUT_DIM / 2]; // fp16 pair-permuted
__device__ __align__(16) uint32_t g_w320p[256];             // W1 row 320, fp16 pairs, A-layout

__device__ __forceinline__ float tf32r(float x) {
    unsigned u; asm("cvt.rna.tf32.f32 %0, %1;" : "=r"(u) : "f"(x));
    return __uint_as_float(u);
}
__device__ __forceinline__ uint32_t packh2(float lo, float hi) {
    uint32_t u; asm("cvt.rn.f16x2.f32 %0, %1, %2;" : "=r"(u) : "f"(hi), "f"(lo));
    return u;
}
__device__ __forceinline__ uint32_t h2_gather(uint32_t pd, uint32_t ps, uint32_t w,
                                              uint32_t d2) {
    uint32_t s, r;
    asm("add.rn.f16x2 %0, %1, %2;" : "=r"(s) : "r"(pd), "r"(ps));
    asm("fma.rn.f16x2 %0, %1, %2, %3;" : "=r"(r) : "r"(d2), "r"(w), "r"(s));
    asm("max.f16x2 %0, %1, %2;" : "=r"(r) : "r"(r), "r"(0u));
    return r;
}
__device__ __forceinline__ void cp16(uint32_t saddr, const void* gptr) {
    asm volatile("cp.async.ca.shared.global [%0], [%1], 16;" :: "r"(saddr), "l"(gptr));
}
__device__ __forceinline__ void cp_commit() { asm volatile("cp.async.commit_group;"); }
template <int N> __device__ __forceinline__ void cp_wait() {
    asm volatile("cp.async.wait_group %0;" :: "n"(N));
}
__device__ __forceinline__ uint32_t s2u(const void* p) {
    uint32_t a;
    asm("{ .reg .u64 t; cvta.to.shared.u64 t, %1; cvt.u32.u64 %0, t; }" : "=r"(a) : "l"(p));
    return a;
}
__device__ __forceinline__ void mma_tf32s(float c[4], const uint32_t a[4],
                                          uint32_t b0, uint32_t b1) {
    asm volatile(
        "mma.sync.aligned.m16n8k8.row.col.f32.tf32.tf32.f32 "
        "{%0,%1,%2,%3}, {%4,%5,%6,%7}, {%8,%9}, {%0,%1,%2,%3};"
        : "+f"(c[0]), "+f"(c[1]), "+f"(c[2]), "+f"(c[3])
        : "r"(a[0]), "r"(a[1]), "r"(a[2]), "r"(a[3]), "r"(b0), "r"(b1));
}
__device__ __forceinline__ void mma_h(float c[4], uint32_t a0, uint32_t a1,
                                      uint32_t a2, uint32_t a3,
                                      uint32_t b0, uint32_t b1) {
    asm volatile(
        "mma.sync.aligned.m16n8k16.row.col.f32.f16.f16.f32 "
        "{%0,%1,%2,%3}, {%4,%5,%6,%7}, {%8,%9}, {%0,%1,%2,%3};"
        : "+f"(c[0]), "+f"(c[1]), "+f"(c[2]), "+f"(c[3])
        : "r"(a0), "r"(a1), "r"(a2), "r"(a3), "r"(b0), "r"(b1));
}
__device__ __forceinline__ int slotp(int p) { return ((p & 3) << 1) | (p >> 2); }
__device__ __forceinline__ int poff(int c) { return ((c >> 4) << 3) + slotp((c >> 1) & 7); }

// ================= prologue 0: weight transforms =================
__global__ void conv_kernel(const float* __restrict__ W1, const float* __restrict__ W2,
                            const float* __restrict__ W3) {
    int i = blockIdx.x * blockDim.x + threadIdx.x;
    if (i < 160 * 512) {
        int r = i >> 9, c = i & 511;
        float v = W1[r * 512 + c];
        if (r >= 32) v += W1[(r + 160) * 512 + c];
        g_W1comb[i] = tf32r(v);
        return;
    }
    i -= 160 * 512;
    if (i < 32 * 512) {
        int r = i >> 9, c = i & 511;
        g_W1c[i] = tf32r(W1[(160 + r) * 512 + c]);
        return;
    }
    i -= 32 * 512;
    if (i < 512 * 512 / 2) {
        int kp = i >> 9, n = i & 511;
        int k = kp << 1;
        g_W2p[(size_t)((kp >> 3) * 512 + n) * 8 + slotp(kp & 7)] =
            packh2(W2[k * 512 + n], W2[(k + 1) * 512 + n]);
        return;
    }
    i -= 512 * 512 / 2;
    if (i < 512 * 256 / 2) {
        int kp = i >> 8, n = i & 255;
        int k = kp << 1;
        g_W3p[(size_t)((kp >> 3) * 256 + n) * 8 + slotp(kp & 7)] =
            packh2(W3[k * 256 + n], W3[(k + 1) * 256 + n]);
        return;
    }
    i -= 512 * 256 / 2;
    if (i < 256) {
        int c = i << 1;
        g_w320p[poff(c)] = packh2(W1[320 * 512 + c], W1[320 * 512 + c + 1]);
    }
}

// ================= prologue GEMM machinery (tf32, proven) =================
template <int N, int NT, int NSTG, int NTHR>
__device__ __forceinline__ void run_gemm(const float* __restrict__ Wg,
                                         const float* __restrict__ As, int lda,
                                         float* Bst, float (&acc)[2][8][4],
                                         int wm, int wn, int g, int tig, int tid) {
    constexpr int BLD = N + 8;
    constexpr int CP_ITERS = (16 * N / 4) / NTHR;
    uint32_t bst_base = s2u(Bst);
#pragma unroll
    for (int mt = 0; mt < 2; mt++)
#pragma unroll
        for (int nt = 0; nt < NT; nt++)
#pragma unroll
            for (int r = 0; r < 4; r++) acc[mt][nt][r] = 0.f;

    auto stage_cp = [&](int s, int buf) {
#pragma unroll
        for (int it = 0; it < CP_ITERS; it++) {
            int idx = it * NTHR + tid;
            int r = idx / (N / 4), c = idx % (N / 4);
            uint32_t dst = bst_base + (uint32_t)((buf * 16 + r) * BLD + c * 4) * 4u;
            cp16(dst, Wg + (size_t)(s * 16 + r) * N + c * 4);
        }
        cp_commit();
    };

    stage_cp(0, 0);
    for (int s = 0; s < NSTG; s++) {
        if (s + 1 < NSTG) { stage_cp(s + 1, (s + 1) & 1); cp_wait<1>(); }
        else              { cp_wait<0>(); }
        __syncthreads();
        const float* B = Bst + (s & 1) * 16 * BLD;
#pragma unroll
        for (int k8 = 0; k8 < 2; k8++) {
            int kg = s * 16 + k8 * 8;
            uint32_t a[2][4];
#pragma unroll
            for (int mt = 0; mt < 2; mt++) {
                const float* ar = As + (wm * 32 + mt * 16 + g) * lda + kg + tig;
                a[mt][0] = __float_as_uint(ar[0]);
                a[mt][1] = __float_as_uint(ar[8 * lda]);
                a[mt][2] = __float_as_uint(ar[4]);
                a[mt][3] = __float_as_uint(ar[8 * lda + 4]);
            }
#pragma unroll
            for (int nt = 0; nt < NT; nt++) {
                int col = wn * (NT * 8) + nt * 8 + g;
                uint32_t b0 = __float_as_uint(B[(k8 * 8 + tig) * BLD + col]);
                uint32_t b1 = __float_as_uint(B[(k8 * 8 + tig + 4) * BLD + col]);
                mma_tf32s(acc[0][nt], a[0], b0, b1);
                mma_tf32s(acc[1][nt], a[1], b0, b1);
            }
        }
        __syncthreads();
    }
}

// ================= prologue 1: per-node PD/PS (fp16 pair output) =================
__global__ void __launch_bounds__(512, 1)
pdps_kernel(const float* __restrict__ nf, const float* __restrict__ nh,
            const float* __restrict__ b1) {
    extern __shared__ float sm[];
    float* As = sm;               // [64][164]
    float* Bst = sm + 64 * 164;   // [2][16][520]
    int tid = threadIdx.x, wid = tid >> 5, lane = tid & 31;
    int g = lane >> 2, tig = lane & 3, wm = wid >> 3, wn = wid & 7;
    int n0 = blockIdx.x * 64;
    {
        int rr = wid * 4;
#pragma unroll
        for (int q = 0; q < 4; q++) {
            int r = rr + q, n = n0 + r;
            bool ok = n < NN; int ni = ok ? n : 0;
            float* ar = As + r * 164;
            ar[lane] = ok ? tf32r(nf[(size_t)ni * 32 + lane]) : 0.f;
#pragma unroll
            for (int j = 0; j < 4; j++)
                ar[32 + j * 32 + lane] = ok ? tf32r(nh[(size_t)ni * 128 + j * 32 + lane]) : 0.f;
            if (lane < 4) ar[160 + lane] = 0.f;
        }
    }
    __syncthreads();
    float acc[2][8][4];
    run_gemm<512, 8, 10, 512>(g_W1comb, As, 164, Bst, acc, wm, wn, g, tig, tid);
#pragma unroll
    for (int mt = 0; mt < 2; mt++)
#pragma unroll
        for (int nt = 0; nt < 8; nt++) {
            int c = wn * 64 + nt * 8 + 2 * tig;
            float bb0 = __ldg(&b1[c]), bb1 = __ldg(&b1[c + 1]);
            int r0 = wm * 32 + mt * 16 + g;
            int off = poff(c);
            if (n0 + r0 < NN)
                g_PDp[(size_t)(n0 + r0) * 256 + off] =
                    packh2(acc[mt][nt][0] + bb0, acc[mt][nt][1] + bb1);
            if (n0 + r0 + 8 < NN)
                g_PDp[(size_t)(n0 + r0 + 8) * 256 + off] =
                    packh2(acc[mt][nt][2] + bb0, acc[mt][nt][3] + bb1);
        }
    run_gemm<512, 8, 2, 512>(g_W1c, As, 164, Bst, acc, wm, wn, g, tig, tid);
#pragma unroll
    for (int mt = 0; mt < 2; mt++)
#pragma unroll
        for (int nt = 0; nt < 8; nt++) {
            int c = wn * 64 + nt * 8 + 2 * tig;
            int r0 = wm * 32 + mt * 16 + g;
            int off = poff(c);
            if (n0 + r0 < NN)
                g_PSp[(size_t)(n0 + r0) * 256 + off] =
                    packh2(acc[mt][nt][0], acc[mt][nt][1]);
            if (n0 + r0 + 8 < NN)
                g_PSp[(size_t)(n0 + r0 + 8) * 256 + off] =
                    packh2(acc[mt][nt][2], acc[mt][nt][3]);
        }
}

// ================= main fused kernel (layers 2+3, 4-buffer / 2-stage sync) ======
// smem u32: Au[0,16896) | Bu[16896, 16896+32768) | sd | ss | sdist
#define SM_AU   0
#define SM_BU   16896
#define SM_SD   49664
#define SM_SS   49728
#define SM_DIST 49792
#define SM_TOT  49856

// 16 k=32 stages in 8 super-stages. 4 B buffers; ONE barrier + ONE wait per
// super-stage; each copy has a full 2-stage MMA body to land.
template <int N, int NT, bool PRELOADED>
__device__ __forceinline__ void gemm_h(const uint32_t* __restrict__ Wp,
                                       const uint32_t* __restrict__ Au, uint32_t* Bu,
                                       float (&acc)[2][8][4],
                                       int wm, int wn, int g, int tig, int tid) {
    constexpr int STGU = 16 * N;                  // u32 per k=32 stage
    constexpr int CPI  = STGU / 4 / THREADS;
    uint32_t bbase = s2u(Bu);
#pragma unroll
    for (int mt = 0; mt < 2; mt++)
#pragma unroll
        for (int nt = 0; nt < NT; nt++)
#pragma unroll
            for (int r = 0; r < 4; r++) acc[mt][nt][r] = 0.f;

    auto docp = [&](int s) {
        const uint32_t* src = Wp + (size_t)s * STGU;
        uint32_t dst = bbase + (uint32_t)((s & 3) * BSTRIDE) * 4u;
#pragma unroll
        for (int it = 0; it < CPI; it++) {
            int idx = it * THREADS + tid;
            cp16(dst + (uint32_t)idx * 16u, src + idx * 4);
        }
        cp_commit();
    };

    if (!PRELOADED) { docp(0); docp(1); }
    const uint32_t* arow0 = Au + (wm * 32 + g) * APITCH + tig * 2;
#pragma unroll 1
    for (int S = 0; S < 8; S++) {
        cp_wait<0>();                 // stages 2S, 2S+1 resident
        __syncthreads();              // buffers (2S+2)&3, (2S+3)&3 fully consumed
        if (2 * S + 2 < 16) { docp(2 * S + 2); docp(2 * S + 3); }
#pragma unroll
        for (int sub = 0; sub < 2; sub++) {
            int s = 2 * S + sub;
            const uint32_t* B = Bu + (s & 3) * BSTRIDE;
#pragma unroll
            for (int kg = 0; kg < 2; kg++) {
                uint2 alo[2], ahi[2];
#pragma unroll
                for (int mt = 0; mt < 2; mt++) {
                    const uint32_t* ar = arow0 + mt * (16 * APITCH) + (s * 2 + kg) * 8;
                    alo[mt] = *(const uint2*)ar;
                    ahi[mt] = *(const uint2*)(ar + 8 * APITCH);
                }
#pragma unroll
                for (int nt = 0; nt < NT; nt++) {
                    int col = wn * (NT * 8) + nt * 8 + g;
                    uint2 pb = *(const uint2*)(B + kg * (N * 8) + col * 8 + tig * 2);
                    mma_h(acc[0][nt], alo[0].x, ahi[0].x, alo[0].y, ahi[0].y, pb.x, pb.y);
                    mma_h(acc[1][nt], alo[1].x, ahi[1].x, alo[1].y, ahi[1].y, pb.x, pb.y);
                }
            }
        }
    }
    __syncthreads();
}

__global__ void __launch_bounds__(THREADS, 1)
edge_kernel(const int* __restrict__ src_idx, const int* __restrict__ dst_idx,
            const float* __restrict__ dist,
            const float* __restrict__ b2, const float* __restrict__ b3,
            float* __restrict__ out, int E) {
    extern __shared__ uint32_t smu[];
    uint32_t* Au = smu + SM_AU;
    uint32_t* Bu = smu + SM_BU;
    int* sd = (int*)(smu + SM_SD);
    int* ss = (int*)(smu + SM_SS);
    float* sdist = (float*)(smu + SM_DIST);

    int tid = threadIdx.x, wid = tid >> 5, lane = tid & 31;
    int g = lane >> 2, tig = lane & 3, wm = wid >> 3, wn = wid & 7;
    int e0 = blockIdx.x * E_TILE;

    // --- issue high-latency index loads first ---
    int my_d = 0, my_s = 0; float my_dist = 0.f;
    if (tid < E_TILE) {
        int e = e0 + tid;
        bool ok = e < E;
        my_d = ok ? dst_idx[e] : 0;
        my_s = ok ? src_idx[e] : 0;
        my_dist = ok ? dist[e] : 0.f;
    }

    // --- preload layer-2 weight stages 0,1 (overlaps index latency + gather) ---
    {
        uint32_t bbase = s2u(Bu);
#pragma unroll
        for (int s = 0; s < 2; s++) {
            const uint32_t* src = g_W2p + (size_t)s * 8192;
            uint32_t dst = bbase + (uint32_t)(s * BSTRIDE) * 4u;
#pragma unroll
            for (int it = 0; it < 4; it++) {
                int idx = it * THREADS + tid;
                cp16(dst + (uint32_t)idx * 16u, src + idx * 4);
            }
            cp_commit();
        }
    }

    if (tid < E_TILE) { sd[tid] = my_d; ss[tid] = my_s; sdist[tid] = my_dist; }
    __syncthreads();

    // ---- gather h1 = relu(PD[dst] + PS[src] + dist*w320) -> Au ----
    {
#pragma unroll
        for (int it = 0; it < 8; it++) {
            int idx4 = it * THREADS + tid;
            int e = idx4 >> 6, i = (idx4 & 63) * 4;
            uint4 pd = *(const uint4*)(g_PDp + (size_t)sd[e] * 256 + i);
            uint4 ps = *(const uint4*)(g_PSp + (size_t)ss[e] * 256 + i);
            uint4 w  = *(const uint4*)(g_w320p + i);
            uint32_t d2 = packh2(sdist[e], sdist[e]);
            uint4 v;
            v.x = h2_gather(pd.x, ps.x, w.x, d2);
            v.y = h2_gather(pd.y, ps.y, w.y, d2);
            v.z = h2_gather(pd.z, ps.z, w.z, d2);
            v.w = h2_gather(pd.w, ps.w, w.w, d2);
            *(uint4*)(Au + e * APITCH + i) = v;
        }
    }
    __syncthreads();

    float acc[2][8][4];

    // ---- layer 2 ----
    gemm_h<HID, 8, true>(g_W2p, Au, Bu, acc, wm, wn, g, tig, tid);
    {
#pragma unroll
        for (int mt = 0; mt < 2; mt++)
#pragma unroll
            for (int nt = 0; nt < 8; nt++) {
                int c = wn * 64 + nt * 8 + 2 * tig;
                float bb0 = __ldg(&b2[c]), bb1 = __ldg(&b2[c + 1]);
                int r0 = wm * 32 + mt * 16 + g;
                int off = poff(c);
                Au[r0 * APITCH + off] =
                    packh2(fmaxf(acc[mt][nt][0] + bb0, 0.f), fmaxf(acc[mt][nt][1] + bb1, 0.f));
                Au[(r0 + 8) * APITCH + off] =
                    packh2(fmaxf(acc[mt][nt][2] + bb0, 0.f), fmaxf(acc[mt][nt][3] + bb1, 0.f));
            }
    }
    __syncthreads();

    // ---- layer 3 ----
    gemm_h<OUT_DIM, 4, false>(g_W3p, Au, Bu, acc, wm, wn, g, tig, tid);
#pragma unroll
    for (int mt = 0; mt < 2; mt++)
#pragma unroll
        for (int nt = 0; nt < 4; nt++) {
            int c0 = wn * 32 + nt * 8 + 2 * tig;
            float bb0 = __ldg(&b3[c0]), bb1 = __ldg(&b3[c0 + 1]);
            int r0 = wm * 32 + mt * 16 + g;
            int edge0 = e0 + r0;
            if (edge0 < E)
                *(float2*)(out + (size_t)edge0 * OUT_DIM + c0) =
                    make_float2(acc[mt][nt][0] + bb0, acc[mt][nt][1] + bb1);
            int edge1 = e0 + r0 + 8;
            if (edge1 < E)
                *(float2*)(out + (size_t)edge1 * OUT_DIM + c0) =
                    make_float2(acc[mt][nt][2] + bb0, acc[mt][nt][3] + bb1);
        }
}

extern "C" void kernel_launch(void* const* d_in, const int* in_sizes, int n_in,
                              void* d_out, int out_size) {
    const float* nf   = (const float*)d_in[0];
    const float* nh   = (const float*)d_in[1];
    const int*   srci = (const int*)d_in[2];
    const int*   dsti = (const int*)d_in[3];
    const float* dist = (const float*)d_in[4];
    const float* W1   = (const float*)d_in[5];
    const float* b1   = (const float*)d_in[6];
    const float* W2   = (const float*)d_in[7];
    const float* b2   = (const float*)d_in[8];
    const float* W3   = (const float*)d_in[9];
    const float* b3   = (const float*)d_in[10];
    float* out = (float*)d_out;
    int E = in_sizes[2];

    const int total_c = 160 * 512 + 32 * 512 + 512 * 512 / 2 + 512 * 256 / 2 + 256;
    conv_kernel<<<(total_c + 511) / 512, 512>>>(W1, W2, W3);

    const int pro_smem = (64 * 164 + 2 * 16 * 520) * (int)sizeof(float);
    cudaFuncSetAttribute(pdps_kernel, cudaFuncAttributeMaxDynamicSharedMemorySize, pro_smem);
    pdps_kernel<<<(NN + 63) / 64, 512, pro_smem>>>(nf, nh, b1);

    const int main_smem = SM_TOT * 4;   // 199,424 bytes
    cudaFuncSetAttribute(edge_kernel, cudaFuncAttributeMaxDynamicSharedMemorySize, main_smem);
    int grid = (E + E_TILE - 1) / E_TILE;
    edge_kernel<<<grid, THREADS, main_smem>>>(srci, dsti, dist, b2, b3, out, E);
}

// round 12
// speedup vs baseline: 1.2273x; 1.0977x over previous
#include <cuda_runtime.h>
#include <cuda_fp16.h>
#include <cstdint>

#define NN      50000
#define HID     512
#define OUT_DIM 256
#define E_TILE  64
#define THREADS 512
#define APITCH  264   // uint32 (fp16-pair) row pitch; conflict-free frag LDS64
#define BSTRIDE 8192  // u32 stride between B buffers (32 KB)

// ---------------- device scratch ----------------
__device__ __align__(16) uint32_t g_PDp[(size_t)NN * 256];  // fp16 pairs, A-layout, incl. +b1
__device__ __align__(16) uint32_t g_PSp[(size_t)NN * 256];  // fp16 pairs, A-layout
__device__ __align__(16) float    g_W1comb[160 * HID];
__device__ __align__(16) float    g_W1c[32 * HID];
__device__ __align__(16) uint32_t g_W2p[HID * HID / 2];     // fp16 pair-permuted
__device__ __align__(16) uint32_t g_W3p[HID * OUT_DIM / 2]; // fp16 pair-permuted
__device__ __align__(16) uint32_t g_w320p[256];             // W1 row 320, fp16 pairs, A-layout

__device__ __forceinline__ float tf32r(float x) {
    unsigned u; asm("cvt.rna.tf32.f32 %0, %1;" : "=r"(u) : "f"(x));
    return __uint_as_float(u);
}
__device__ __forceinline__ uint32_t packh2(float lo, float hi) {
    uint32_t u; asm("cvt.rn.f16x2.f32 %0, %1, %2;" : "=r"(u) : "f"(hi), "f"(lo));
    return u;
}
__device__ __forceinline__ uint32_t h2_gather(uint32_t pd, uint32_t ps, uint32_t w,
                                              uint32_t d2) {
    uint32_t s, r;
    asm("add.rn.f16x2 %0, %1, %2;" : "=r"(s) : "r"(pd), "r"(ps));
    asm("fma.rn.f16x2 %0, %1, %2, %3;" : "=r"(r) : "r"(d2), "r"(w), "r"(s));
    asm("max.f16x2 %0, %1, %2;" : "=r"(r) : "r"(r), "r"(0u));
    return r;
}
__device__ __forceinline__ void cp16(uint32_t saddr, const void* gptr) {
    asm volatile("cp.async.ca.shared.global [%0], [%1], 16;" :: "r"(saddr), "l"(gptr));
}
__device__ __forceinline__ void cp_commit() { asm volatile("cp.async.commit_group;"); }
template <int N> __device__ __forceinline__ void cp_wait() {
    asm volatile("cp.async.wait_group %0;" :: "n"(N));
}
__device__ __forceinline__ uint32_t s2u(const void* p) {
    uint32_t a;
    asm("{ .reg .u64 t; cvta.to.shared.u64 t, %1; cvt.u32.u64 %0, t; }" : "=r"(a) : "l"(p));
    return a;
}
__device__ __forceinline__ void mma_tf32s(float c[4], const uint32_t a[4],
                                          uint32_t b0, uint32_t b1) {
    asm volatile(
        "mma.sync.aligned.m16n8k8.row.col.f32.tf32.tf32.f32 "
        "{%0,%1,%2,%3}, {%4,%5,%6,%7}, {%8,%9}, {%0,%1,%2,%3};"
        : "+f"(c[0]), "+f"(c[1]), "+f"(c[2]), "+f"(c[3])
        : "r"(a[0]), "r"(a[1]), "r"(a[2]), "r"(a[3]), "r"(b0), "r"(b1));
}
__device__ __forceinline__ void mma_h(float c[4], uint32_t a0, uint32_t a1,
                                      uint32_t a2, uint32_t a3,
                                      uint32_t b0, uint32_t b1) {
    asm volatile(
        "mma.sync.aligned.m16n8k16.row.col.f32.f16.f16.f32 "
        "{%0,%1,%2,%3}, {%4,%5,%6,%7}, {%8,%9}, {%0,%1,%2,%3};"
        : "+f"(c[0]), "+f"(c[1]), "+f"(c[2]), "+f"(c[3])
        : "r"(a0), "r"(a1), "r"(a2), "r"(a3), "r"(b0), "r"(b1));
}
__device__ __forceinline__ int slotp(int p) { return ((p & 3) << 1) | (p >> 2); }
__device__ __forceinline__ int poff(int c) { return ((c >> 4) << 3) + slotp((c >> 1) & 7); }

// ================= prologue 0: weight transforms =================
__global__ void conv_kernel(const float* __restrict__ W1, const float* __restrict__ W2,
                            const float* __restrict__ W3) {
    int i = blockIdx.x * blockDim.x + threadIdx.x;
    if (i < 160 * 512) {
        int r = i >> 9, c = i & 511;
        float v = W1[r * 512 + c];
        if (r >= 32) v += W1[(r + 160) * 512 + c];
        g_W1comb[i] = tf32r(v);
        return;
    }
    i -= 160 * 512;
    if (i < 32 * 512) {
        int r = i >> 9, c = i & 511;
        g_W1c[i] = tf32r(W1[(160 + r) * 512 + c]);
        return;
    }
    i -= 32 * 512;
    if (i < 512 * 512 / 2) {
        int kp = i >> 9, n = i & 511;
        int k = kp << 1;
        g_W2p[(size_t)((kp >> 3) * 512 + n) * 8 + slotp(kp & 7)] =
            packh2(W2[k * 512 + n], W2[(k + 1) * 512 + n]);
        return;
    }
    i -= 512 * 512 / 2;
    if (i < 512 * 256 / 2) {
        int kp = i >> 8, n = i & 255;
        int k = kp << 1;
        g_W3p[(size_t)((kp >> 3) * 256 + n) * 8 + slotp(kp & 7)] =
            packh2(W3[k * 256 + n], W3[(k + 1) * 256 + n]);
        return;
    }
    i -= 512 * 256 / 2;
    if (i < 256) {
        int c = i << 1;
        g_w320p[poff(c)] = packh2(W1[320 * 512 + c], W1[320 * 512 + c + 1]);
    }
}

// ================= prologue GEMM machinery (tf32, proven) =================
template <int N, int NT, int NSTG, int NTHR>
__device__ __forceinline__ void run_gemm(const float* __restrict__ Wg,
                                         const float* __restrict__ As, int lda,
                                         float* Bst, float (&acc)[2][8][4],
                                         int wm, int wn, int g, int tig, int tid) {
    constexpr int BLD = N + 8;
    constexpr int CP_ITERS = (16 * N / 4) / NTHR;
    uint32_t bst_base = s2u(Bst);
#pragma unroll
    for (int mt = 0; mt < 2; mt++)
#pragma unroll
        for (int nt = 0; nt < NT; nt++)
#pragma unroll
            for (int r = 0; r < 4; r++) acc[mt][nt][r] = 0.f;

    auto stage_cp = [&](int s, int buf) {
#pragma unroll
        for (int it = 0; it < CP_ITERS; it++) {
            int idx = it * NTHR + tid;
            int r = idx / (N / 4), c = idx % (N / 4);
            uint32_t dst = bst_base + (uint32_t)((buf * 16 + r) * BLD + c * 4) * 4u;
            cp16(dst, Wg + (size_t)(s * 16 + r) * N + c * 4);
        }
        cp_commit();
    };

    stage_cp(0, 0);
    for (int s = 0; s < NSTG; s++) {
        if (s + 1 < NSTG) { stage_cp(s + 1, (s + 1) & 1); cp_wait<1>(); }
        else              { cp_wait<0>(); }
        __syncthreads();
        const float* B = Bst + (s & 1) * 16 * BLD;
#pragma unroll
        for (int k8 = 0; k8 < 2; k8++) {
            int kg = s * 16 + k8 * 8;
            uint32_t a[2][4];
#pragma unroll
            for (int mt = 0; mt < 2; mt++) {
                const float* ar = As + (wm * 32 + mt * 16 + g) * lda + kg + tig;
                a[mt][0] = __float_as_uint(ar[0]);
                a[mt][1] = __float_as_uint(ar[8 * lda]);
                a[mt][2] = __float_as_uint(ar[4]);
                a[mt][3] = __float_as_uint(ar[8 * lda + 4]);
            }
#pragma unroll
            for (int nt = 0; nt < NT; nt++) {
                int col = wn * (NT * 8) + nt * 8 + g;
                uint32_t b0 = __float_as_uint(B[(k8 * 8 + tig) * BLD + col]);
                uint32_t b1 = __float_as_uint(B[(k8 * 8 + tig + 4) * BLD + col]);
                mma_tf32s(acc[0][nt], a[0], b0, b1);
                mma_tf32s(acc[1][nt], a[1], b0, b1);
            }
        }
        __syncthreads();
    }
}

// ================= prologue 1: per-node PD/PS (fp16 pair output) =================
__global__ void __launch_bounds__(512, 1)
pdps_kernel(const float* __restrict__ nf, const float* __restrict__ nh,
            const float* __restrict__ b1) {
    extern __shared__ float sm[];
    float* As = sm;               // [64][164]
    float* Bst = sm + 64 * 164;   // [2][16][520]
    int tid = threadIdx.x, wid = tid >> 5, lane = tid & 31;
    int g = lane >> 2, tig = lane & 3, wm = wid >> 3, wn = wid & 7;
    int n0 = blockIdx.x * 64;
    {
        int rr = wid * 4;
#pragma unroll
        for (int q = 0; q < 4; q++) {
            int r = rr + q, n = n0 + r;
            bool ok = n < NN; int ni = ok ? n : 0;
            float* ar = As + r * 164;
            ar[lane] = ok ? tf32r(nf[(size_t)ni * 32 + lane]) : 0.f;
#pragma unroll
            for (int j = 0; j < 4; j++)
                ar[32 + j * 32 + lane] = ok ? tf32r(nh[(size_t)ni * 128 + j * 32 + lane]) : 0.f;
            if (lane < 4) ar[160 + lane] = 0.f;
        }
    }
    __syncthreads();
    float acc[2][8][4];
    run_gemm<512, 8, 10, 512>(g_W1comb, As, 164, Bst, acc, wm, wn, g, tig, tid);
#pragma unroll
    for (int mt = 0; mt < 2; mt++)
#pragma unroll
        for (int nt = 0; nt < 8; nt++) {
            int c = wn * 64 + nt * 8 + 2 * tig;
            float bb0 = __ldg(&b1[c]), bb1 = __ldg(&b1[c + 1]);
            int r0 = wm * 32 + mt * 16 + g;
            int off = poff(c);
            if (n0 + r0 < NN)
                g_PDp[(size_t)(n0 + r0) * 256 + off] =
                    packh2(acc[mt][nt][0] + bb0, acc[mt][nt][1] + bb1);
            if (n0 + r0 + 8 < NN)
                g_PDp[(size_t)(n0 + r0 + 8) * 256 + off] =
                    packh2(acc[mt][nt][2] + bb0, acc[mt][nt][3] + bb1);
        }
    run_gemm<512, 8, 2, 512>(g_W1c, As, 164, Bst, acc, wm, wn, g, tig, tid);
#pragma unroll
    for (int mt = 0; mt < 2; mt++)
#pragma unroll
        for (int nt = 0; nt < 8; nt++) {
            int c = wn * 64 + nt * 8 + 2 * tig;
            int r0 = wm * 32 + mt * 16 + g;
            int off = poff(c);
            if (n0 + r0 < NN)
                g_PSp[(size_t)(n0 + r0) * 256 + off] =
                    packh2(acc[mt][nt][0], acc[mt][nt][1]);
            if (n0 + r0 + 8 < NN)
                g_PSp[(size_t)(n0 + r0 + 8) * 256 + off] =
                    packh2(acc[mt][nt][2], acc[mt][nt][3]);
        }
}

// ================= main fused kernel (layers 2+3) =================
// smem u32: Au[0,16896) | Bu[16896, 16896+32768) | sd | ss | sdist
#define SM_AU   0
#define SM_BU   16896
#define SM_SD   49664
#define SM_SS   49728
#define SM_DIST 49792
#define SM_TOT  49856

// one k=32 MMA stage for layer 2 (N=512, NT=8)
__device__ __forceinline__ void mma_stage_l2(const uint32_t* arow0, const uint32_t* B,
                                             int s, int wn, int g, int tig,
                                             float (&acc)[2][8][4]) {
#pragma unroll
    for (int kg = 0; kg < 2; kg++) {
        uint2 alo[2], ahi[2];
#pragma unroll
        for (int mt = 0; mt < 2; mt++) {
            const uint32_t* ar = arow0 + mt * (16 * APITCH) + (s * 2 + kg) * 8;
            alo[mt] = *(const uint2*)ar;
            ahi[mt] = *(const uint2*)(ar + 8 * APITCH);
        }
#pragma unroll
        for (int nt = 0; nt < 8; nt++) {
            int col = wn * 64 + nt * 8 + g;
            uint2 pb = *(const uint2*)(B + kg * (512 * 8) + col * 8 + tig * 2);
            mma_h(acc[0][nt], alo[0].x, ahi[0].x, alo[0].y, ahi[0].y, pb.x, pb.y);
            mma_h(acc[1][nt], alo[1].x, ahi[1].x, alo[1].y, ahi[1].y, pb.x, pb.y);
        }
    }
}

// layer-2 GEMM with fused gather pipeline: during super-stage S, gather h1
// chunk S+2 (hidden under the MMA bodies). Super-stage 7 preloads W3 stages 0,1.
__device__ __forceinline__ void gemm_l2(uint32_t* Au, uint32_t* Bu,
                                        float (&acc)[2][8][4],
                                        int wm, int wn, int g, int tig, int tid,
                                        const uint32_t* pdb, const uint32_t* psb,
                                        uint32_t d2) {
    uint32_t bbase = s2u(Bu);
#pragma unroll
    for (int mt = 0; mt < 2; mt++)
#pragma unroll
        for (int nt = 0; nt < 8; nt++)
#pragma unroll
            for (int r = 0; r < 4; r++) acc[mt][nt][r] = 0.f;

    auto docp2 = [&](int s) {
        const uint32_t* src = g_W2p + (size_t)s * 8192;
        uint32_t dst = bbase + (uint32_t)((s & 3) * BSTRIDE) * 4u;
#pragma unroll
        for (int it = 0; it < 4; it++) {
            int idx = it * THREADS + tid;
            cp16(dst + (uint32_t)idx * 16u, src + idx * 4);
        }
        cp_commit();
    };

    const uint32_t* arow0 = Au + (wm * 32 + g) * APITCH + tig * 2;
    uint32_t* Auw = Au + (tid >> 3) * APITCH;
    int il = (tid & 7) * 4;
#pragma unroll 1
    for (int S = 0; S < 8; S++) {
        cp_wait<0>();
        __syncthreads();
        if (S < 7) { docp2(2 * S + 2); docp2(2 * S + 3); }
        else {
            // preload W3 stages 0,1 into buffers 0,1 (freed since super-stage 6)
#pragma unroll
            for (int s3 = 0; s3 < 2; s3++) {
                const uint32_t* src = g_W3p + (size_t)s3 * 4096;
                uint32_t dst = bbase + (uint32_t)(s3 * BSTRIDE) * 4u;
#pragma unroll
                for (int it = 0; it < 2; it++) {
                    int idx = it * THREADS + tid;
                    cp16(dst + (uint32_t)idx * 16u, src + idx * 4);
                }
                cp_commit();
            }
        }

        int cc = S + 2;
        bool dog = cc < 8;
        int ioff = cc * 32 + il;
        uint4 pd, ps, w;
        if (dog) {                      // LDGs issued; latency hidden by MMA block
            pd = *(const uint4*)(pdb + ioff);
            ps = *(const uint4*)(psb + ioff);
            w  = __ldg((const uint4*)(g_w320p + ioff));
        }

        mma_stage_l2(arow0, Bu + ((2 * S) & 3) * BSTRIDE, 2 * S, wn, g, tig, acc);

        if (dog) {
            uint4 v;
            v.x = h2_gather(pd.x, ps.x, w.x, d2);
            v.y = h2_gather(pd.y, ps.y, w.y, d2);
            v.z = h2_gather(pd.z, ps.z, w.z, d2);
            v.w = h2_gather(pd.w, ps.w, w.w, d2);
            *(uint4*)(Auw + ioff) = v;
        }

        mma_stage_l2(arow0, Bu + ((2 * S + 1) & 3) * BSTRIDE, 2 * S + 1, wn, g, tig, acc);
    }
    __syncthreads();
}

// layer-3 GEMM (N=256, NT=4), 4-buffer / 2-stage sync, stages 0,1 preloaded.
__device__ __forceinline__ void gemm_l3(const uint32_t* __restrict__ Au, uint32_t* Bu,
                                        float (&acc)[2][8][4],
                                        int wm, int wn, int g, int tig, int tid) {
    constexpr int STGU = 16 * OUT_DIM;            // 4096 u32
    uint32_t bbase = s2u(Bu);
#pragma unroll
    for (int mt = 0; mt < 2; mt++)
#pragma unroll
        for (int nt = 0; nt < 4; nt++)
#pragma unroll
            for (int r = 0; r < 4; r++) acc[mt][nt][r] = 0.f;

    auto docp = [&](int s) {
        const uint32_t* src = g_W3p + (size_t)s * STGU;
        uint32_t dst = bbase + (uint32_t)((s & 3) * BSTRIDE) * 4u;
#pragma unroll
        for (int it = 0; it < 2; it++) {
            int idx = it * THREADS + tid;
            cp16(dst + (uint32_t)idx * 16u, src + idx * 4);
        }
        cp_commit();
    };

    const uint32_t* arow0 = Au + (wm * 32 + g) * APITCH + tig * 2;
#pragma unroll 1
    for (int S = 0; S < 8; S++) {
        cp_wait<0>();
        __syncthreads();
        if (2 * S + 2 < 16) { docp(2 * S + 2); docp(2 * S + 3); }
#pragma unroll
        for (int sub = 0; sub < 2; sub++) {
            int s = 2 * S + sub;
            const uint32_t* B = Bu + (s & 3) * BSTRIDE;
#pragma unroll
            for (int kg = 0; kg < 2; kg++) {
                uint2 alo[2], ahi[2];
#pragma unroll
                for (int mt = 0; mt < 2; mt++) {
                    const uint32_t* ar = arow0 + mt * (16 * APITCH) + (s * 2 + kg) * 8;
                    alo[mt] = *(const uint2*)ar;
                    ahi[mt] = *(const uint2*)(ar + 8 * APITCH);
                }
#pragma unroll
                for (int nt = 0; nt < 4; nt++) {
                    int col = wn * 32 + nt * 8 + g;
                    uint2 pb = *(const uint2*)(B + kg * (OUT_DIM * 8) + col * 8 + tig * 2);
                    mma_h(acc[0][nt], alo[0].x, ahi[0].x, alo[0].y, ahi[0].y, pb.x, pb.y);
                    mma_h(acc[1][nt], alo[1].x, ahi[1].x, alo[1].y, ahi[1].y, pb.x, pb.y);
                }
            }
        }
    }
    __syncthreads();
}

__global__ void __launch_bounds__(THREADS, 1)
edge_kernel(const int* __restrict__ src_idx, const int* __restrict__ dst_idx,
            const float* __restrict__ dist,
            const float* __restrict__ b2, const float* __restrict__ b3,
            float* __restrict__ out, int E) {
    extern __shared__ uint32_t smu[];
    uint32_t* Au = smu + SM_AU;
    uint32_t* Bu = smu + SM_BU;
    int* sd = (int*)(smu + SM_SD);
    int* ss = (int*)(smu + SM_SS);
    float* sdist = (float*)(smu + SM_DIST);

    int tid = threadIdx.x, wid = tid >> 5, lane = tid & 31;
    int g = lane >> 2, tig = lane & 3, wm = wid >> 3, wn = wid & 7;
    int e0 = blockIdx.x * E_TILE;

    // --- issue high-latency index loads first ---
    int my_d = 0, my_s = 0; float my_dist = 0.f;
    if (tid < E_TILE) {
        int e = e0 + tid;
        bool ok = e < E;
        my_d = ok ? dst_idx[e] : 0;
        my_s = ok ? src_idx[e] : 0;
        my_dist = ok ? dist[e] : 0.f;
    }

    // --- preload layer-2 weight stages 0,1 (overlaps index latency + gather) ---
    {
        uint32_t bbase = s2u(Bu);
#pragma unroll
        for (int s = 0; s < 2; s++) {
            const uint32_t* src = g_W2p + (size_t)s * 8192;
            uint32_t dst = bbase + (uint32_t)(s * BSTRIDE) * 4u;
#pragma unroll
            for (int it = 0; it < 4; it++) {
                int idx = it * THREADS + tid;
                cp16(dst + (uint32_t)idx * 16u, src + idx * 4);
            }
            cp_commit();
        }
    }

    if (tid < E_TILE) { sd[tid] = my_d; ss[tid] = my_s; sdist[tid] = my_dist; }
    __syncthreads();

    // --- per-thread gather bindings (edge = tid>>3 fixed for whole tile) ---
    int ge = tid >> 3, il = (tid & 7) * 4;
    const uint32_t* pdb = g_PDp + (size_t)sd[ge] * 256;
    const uint32_t* psb = g_PSp + (size_t)ss[ge] * 256;
    uint32_t d2 = packh2(sdist[ge], sdist[ge]);
    uint32_t* Auw = Au + ge * APITCH;

    // ---- prologue gather: chunks 0,1 only (rest pipelined into layer 2) ----
#pragma unroll
    for (int c = 0; c < 2; c++) {
        int i = c * 32 + il;
        uint4 pd = *(const uint4*)(pdb + i);
        uint4 ps = *(const uint4*)(psb + i);
        uint4 w  = __ldg((const uint4*)(g_w320p + i));
        uint4 v;
        v.x = h2_gather(pd.x, ps.x, w.x, d2);
        v.y = h2_gather(pd.y, ps.y, w.y, d2);
        v.z = h2_gather(pd.z, ps.z, w.z, d2);
        v.w = h2_gather(pd.w, ps.w, w.w, d2);
        *(uint4*)(Auw + i) = v;
    }
    __syncthreads();

    float acc[2][8][4];

    // ---- layer 2 (gather chunks 2..7 fused into the mainloop) ----
    gemm_l2(Au, Bu, acc, wm, wn, g, tig, tid, pdb, psb, d2);
    {
#pragma unroll
        for (int mt = 0; mt < 2; mt++)
#pragma unroll
            for (int nt = 0; nt < 8; nt++) {
                int c = wn * 64 + nt * 8 + 2 * tig;
                float bb0 = __ldg(&b2[c]), bb1 = __ldg(&b2[c + 1]);
                int r0 = wm * 32 + mt * 16 + g;
                int off = poff(c);
                Au[r0 * APITCH + off] =
                    packh2(fmaxf(acc[mt][nt][0] + bb0, 0.f), fmaxf(acc[mt][nt][1] + bb1, 0.f));
                Au[(r0 + 8) * APITCH + off] =
                    packh2(fmaxf(acc[mt][nt][2] + bb0, 0.f), fmaxf(acc[mt][nt][3] + bb1, 0.f));
            }
    }
    __syncthreads();

    // ---- layer 3 (stages 0,1 already preloaded by gemm_l2's last super-stage) ----
    gemm_l3(Au, Bu, acc, wm, wn, g, tig, tid);
#pragma unroll
    for (int mt = 0; mt < 2; mt++)
#pragma unroll
        for (int nt = 0; nt < 4; nt++) {
            int c0 = wn * 32 + nt * 8 + 2 * tig;
            float bb0 = __ldg(&b3[c0]), bb1 = __ldg(&b3[c0 + 1]);
            int r0 = wm * 32 + mt * 16 + g;
            int edge0 = e0 + r0;
            if (edge0 < E)
                *(float2*)(out + (size_t)edge0 * OUT_DIM + c0) =
                    make_float2(acc[mt][nt][0] + bb0, acc[mt][nt][1] + bb1);
            int edge1 = e0 + r0 + 8;
            if (edge1 < E)
                *(float2*)(out + (size_t)edge1 * OUT_DIM + c0) =
                    make_float2(acc[mt][nt][2] + bb0, acc[mt][nt][3] + bb1);
        }
}

extern "C" void kernel_launch(void* const* d_in, const int* in_sizes, int n_in,
                              void* d_out, int out_size) {
    const float* nf   = (const float*)d_in[0];
    const float* nh   = (const float*)d_in[1];
    const int*   srci = (const int*)d_in[2];
    const int*   dsti = (const int*)d_in[3];
    const float* dist = (const float*)d_in[4];
    const float* W1   = (const float*)d_in[5];
    const float* b1   = (const float*)d_in[6];
    const float* W2   = (const float*)d_in[7];
    const float* b2   = (const float*)d_in[8];
    const float* W3   = (const float*)d_in[9];
    const float* b3   = (const float*)d_in[10];
    float* out = (float*)d_out;
    int E = in_sizes[2];

    const int total_c = 160 * 512 + 32 * 512 + 512 * 512 / 2 + 512 * 256 / 2 + 256;
    conv_kernel<<<(total_c + 511) / 512, 512>>>(W1, W2, W3);

    const int pro_smem = (64 * 164 + 2 * 16 * 520) * (int)sizeof(float);
    cudaFuncSetAttribute(pdps_kernel, cudaFuncAttributeMaxDynamicSharedMemorySize, pro_smem);
    pdps_kernel<<<(NN + 63) / 64, 512, pro_smem>>>(nf, nh, b1);

    const int main_smem = SM_TOT * 4;   // 199,424 bytes
    cudaFuncSetAttribute(edge_kernel, cudaFuncAttributeMaxDynamicSharedMemorySize, main_smem);
    int grid = (E + E_TILE - 1) / E_TILE;
    edge_kernel<<<grid, THREADS, main_smem>>>(srci, dsti, dist, b2, b3, out, E);
}